// round 12
// baseline (speedup 1.0000x reference)
#include <cuda_runtime.h>
#include <cuda_fp16.h>
#include <math.h>
#include <stdint.h>

// ---------------- problem constants ----------------
#define L_    2
#define D_    256
#define DFF_  1024
#define NH_   8
#define NP_   4
#define CIN_  512
#define B_    8
#define HH_   64
#define WW_   64
#define HW_   4096
#define EPS_  1e-5f

// ---------------- GEMM tiling ----------------
#define BM 128
#define BN 128
#define BK 32
// block-of-128B layout: (r, c16) -> (r>>3)*256 + c16*64 + (r&7)*8   [halfs]
#define STAGE_H (BM * BK)     // 4096 halfs = 8KB per stage

// ---------------- scratch (device globals; allocation-free) ----------------
__device__ __align__(128) float  g_q     [B_*HW_*D_];     // fp32 residual master
__device__ __align__(128) float  g_tmp   [B_*HW_*D_];     // fp32 GEMM out for LN
__device__ __align__(128) float  g_logits[B_*HW_*128];
__device__ __align__(128) float  g_loc   [B_*HW_*NH_*NP_*2];
__device__ __align__(128) float  g_attw  [B_*HW_*NH_*NP_];
__device__ __align__(128) float  g_bcat  [L_*128];

__device__ __align__(128) __half h_x    [B_*HW_*CIN_];    // x transposed [b][hw][c]
__device__ __align__(128) __half h_src  [B_*HW_*D_];
__device__ __align__(128) __half h_q    [B_*HW_*D_];
__device__ __align__(128) __half h_val  [B_*HW_*D_];
__device__ __align__(128) __half h_samp [B_*HW_*D_];
__device__ __align__(128) __half h_ffn  [B_*HW_*DFF_];

__device__ __align__(128) __half h_Win  [D_*CIN_];        // [D][CIN]
__device__ __align__(128) __half h_Wout [CIN_*D_];        // [CIN][D]
__device__ __align__(128) __half h_WvalT[L_*D_*D_];       // [n][k]
__device__ __align__(128) __half h_WoT  [L_*D_*D_];
__device__ __align__(128) __half h_W1T  [L_*DFF_*D_];     // [DFF][D]
__device__ __align__(128) __half h_W2T  [L_*D_*DFF_];     // [D][DFF]
__device__ __align__(128) __half h_wcatT[L_*128*D_];      // [128][D]

// ---------------- helpers ----------------
__device__ __forceinline__ void cp16(void* dst, const void* src) {
    uint32_t d = (uint32_t)__cvta_generic_to_shared(dst);
    asm volatile("cp.async.cg.shared.global [%0], [%1], 16;\n" :: "r"(d), "l"(src));
}
__device__ __forceinline__ void mma16(float* c, const uint32_t* a, const uint32_t* b) {
    asm volatile(
        "mma.sync.aligned.m16n8k16.row.col.f32.f16.f16.f32 "
        "{%0,%1,%2,%3},{%4,%5,%6,%7},{%8,%9},{%0,%1,%2,%3};"
        : "+f"(c[0]), "+f"(c[1]), "+f"(c[2]), "+f"(c[3])
        : "r"(a[0]), "r"(a[1]), "r"(a[2]), "r"(a[3]), "r"(b[0]), "r"(b[1]));
}
#define LDSM4(r0, r1, r2, r3, addr) \
    asm volatile("ldmatrix.sync.aligned.m8n8.x4.shared.b16 {%0,%1,%2,%3}, [%4];" \
        : "=r"(r0), "=r"(r1), "=r"(r2), "=r"(r3) : "r"(addr))

// ============================================================
// fp16 tensor-core GEMM. C[M,N] = A[M,K] @ B^T + epilogue
//  A: fp16 row-major [M][K] (lda); B: fp16 [N][K] (ldb) -> .col operand
//  EPI 0: +bias(optional relu); 1: BN per-n + relu; 2: BN per-m + relu
//  OUTH 1: store fp16; 0: store fp32
// 3-stage cp.async, tile 128x128x32, 8 warps (2x4), warp tile 64x32.
// SMEM in 128B-block layout; fragments loaded with ldmatrix.x4.
// ============================================================
template<int EPI, int OUTH>
__global__ void __launch_bounds__(256) gemm_h(
    const __half* __restrict__ A, int lda, size_t sA,
    const __half* __restrict__ Bh, int ldb, size_t sB,
    void* __restrict__ C, int ldc, size_t sC,
    const float* __restrict__ p0, const float* __restrict__ p1,
    const float* __restrict__ p2, const float* __restrict__ p3,
    int K, int relu)
{
    extern __shared__ __half smem[];
    __half* As = smem;                       // 3 stages of STAGE_H
    __half* Bs = smem + 3 * STAGE_H;
    uint32_t aBase = (uint32_t)__cvta_generic_to_shared(As);
    uint32_t bBase = (uint32_t)__cvta_generic_to_shared(Bs);

    int tid = threadIdx.x;
    int bm = blockIdx.x * BM, bn = blockIdx.y * BN;
    const __half* Ab = A  + (size_t)blockIdx.z * sA;
    const __half* Bb = Bh + (size_t)blockIdx.z * sB;

    float acc[4][4][4];
#pragma unroll
    for (int i = 0; i < 4; i++)
#pragma unroll
        for (int j = 0; j < 4; j++)
#pragma unroll
            for (int r = 0; r < 4; r++) acc[i][j][r] = 0.f;

    int lane = tid & 31, wid = tid >> 5;
    int wm = (wid >> 2) * 64, wn = (wid & 3) * 32;
    int grp = lane >> 2, tig = lane & 3;

    // per-lane ldmatrix address offsets (bytes within a stage)
    // A: lanes 0-7 -> (m 0-7, c0); 8-15 -> (m 8-15, c0); 16-23 -> (m 0-7, c1); 24-31 -> (m 8-15, c1)
    int lArow = lane & 15;
    int lAoff = ((lArow >> 3) * 512) + ((lane >> 4) * 128) + ((lArow & 7) * 16);
    // B: lanes 0-7 -> (n 0-7, c0); 8-15 -> (n 0-7, c1); 16-23 -> (n 8-15, c0); 24-31 -> (n 8-15, c1)
    int lBrow = ((lane >> 4) << 3) + (lane & 7);
    int lBoff = ((lBrow >> 3) * 512) + (((lane >> 3) & 1) * 128) + ((lBrow & 7) * 16);

    auto stage = [&](int s, int k0) {
        __half* Asl = As + s * STAGE_H;
        __half* Bsl = Bs + s * STAGE_H;
#pragma unroll
        for (int id = tid; id < 512; id += 256) {
            int r = id & 127, c = id >> 7;
            cp16(&Asl[(r >> 3) * 256 + c * 64 + (r & 7) * 8],
                 Ab + (size_t)(bm + r) * lda + k0 + c * 8);
        }
#pragma unroll
        for (int id = tid; id < 512; id += 256) {
            int r = id & 127, c = id >> 7;
            cp16(&Bsl[(r >> 3) * 256 + c * 64 + (r & 7) * 8],
                 Bb + (size_t)(bn + r) * ldb + k0 + c * 8);
        }
        asm volatile("cp.async.commit_group;\n");
    };

    stage(0, 0);
    stage(1, BK);

    int slot = 0;
    for (int k0 = 0; k0 < K; k0 += BK) {
        if (k0 + BK < K) asm volatile("cp.async.wait_group 1;\n");
        else             asm volatile("cp.async.wait_group 0;\n");
        __syncthreads();
        if (k0 + 2 * BK < K) {
            int ns = slot + 2; if (ns >= 3) ns -= 3;
            stage(ns, k0 + 2 * BK);
        }

        uint32_t aS = aBase + slot * (STAGE_H * 2);
        uint32_t bS = bBase + slot * (STAGE_H * 2);
#pragma unroll
        for (int ks = 0; ks < 2; ks++) {
            uint32_t af[4][4], bf[4][2];
#pragma unroll
            for (int mt = 0; mt < 4; mt++) {
                uint32_t addr = aS + (wm + mt * 16) * 64 + ks * 256 + lAoff;
                LDSM4(af[mt][0], af[mt][1], af[mt][2], af[mt][3], addr);
            }
#pragma unroll
            for (int pr = 0; pr < 2; pr++) {
                uint32_t addr = bS + (wn + pr * 16) * 64 + ks * 256 + lBoff;
                LDSM4(bf[pr * 2][0], bf[pr * 2][1], bf[pr * 2 + 1][0], bf[pr * 2 + 1][1], addr);
            }
#pragma unroll
            for (int mt = 0; mt < 4; mt++)
#pragma unroll
                for (int nt = 0; nt < 4; nt++)
                    mma16(acc[mt][nt], af[mt], bf[nt]);
        }
        slot++; if (slot >= 3) slot -= 3;
    }

    // ---------------- epilogue ----------------
#pragma unroll
    for (int mt = 0; mt < 4; mt++) {
#pragma unroll
        for (int nt = 0; nt < 4; nt++) {
            int gm = bm + wm + mt * 16 + grp;
            int gn = bn + wn + nt * 8 + tig * 2;
            float* c = acc[mt][nt];
#pragma unroll
            for (int half = 0; half < 2; half++) {
                int row = gm + half * 8;
                float v0 = c[half * 2 + 0], v1 = c[half * 2 + 1];
                if (EPI == 0) {
                    v0 += p0[gn]; v1 += p0[gn + 1];
                    if (relu) { v0 = fmaxf(v0, 0.f); v1 = fmaxf(v1, 0.f); }
                } else if (EPI == 1) {
                    float s0 = rsqrtf(p3[gn] + EPS_) * p0[gn];
                    float s1 = rsqrtf(p3[gn + 1] + EPS_) * p0[gn + 1];
                    v0 = fmaxf((v0 - p2[gn]) * s0 + p1[gn], 0.f);
                    v1 = fmaxf((v1 - p2[gn + 1]) * s1 + p1[gn + 1], 0.f);
                } else {
                    float s = rsqrtf(p3[row] + EPS_) * p0[row];
                    float h = p1[row] - p2[row] * s;
                    v0 = fmaxf(v0 * s + h, 0.f);
                    v1 = fmaxf(v1 * s + h, 0.f);
                }
                size_t off = (size_t)((size_t)blockIdx.z * sC) + (size_t)row * ldc + gn;
                if (OUTH) {
                    __half2 hv = __floats2half2_rn(v0, v1);
                    *(__half2*)((__half*)C + off) = hv;
                } else {
                    float2 o; o.x = v0; o.y = v1;
                    *(float2*)((float*)C + off) = o;
                }
            }
        }
    }
}

// ============================================================
// prep: fp32 -> fp16 convert (same layout)
// ============================================================
__global__ void cvt_h_kernel(const float* __restrict__ src, __half* __restrict__ dst, int n)
{
    int i = blockIdx.x * blockDim.x + threadIdx.x;
    if (i < n) dst[i] = __float2half(src[i]);
}

// ============================================================
// prep: transpose + convert  src fp32 [R][C] -> dst fp16 [C][R], batched
// ============================================================
__global__ void transpose_h_kernel(const float* __restrict__ src, __half* __restrict__ dst,
                                   int R, int C, size_t ssrc, size_t sdst)
{
    __shared__ float t[32][33];
    const float* s = src + (size_t)blockIdx.z * ssrc;
    __half* d = dst + (size_t)blockIdx.z * sdst;
    int r0 = blockIdx.y * 32, c0 = blockIdx.x * 32;
    int tx = threadIdx.x, ty = threadIdx.y;
#pragma unroll
    for (int i = 0; i < 32; i += 8)
        t[ty + i][tx] = s[(size_t)(r0 + ty + i) * C + c0 + tx];
    __syncthreads();
#pragma unroll
    for (int i = 0; i < 32; i += 8)
        d[(size_t)(c0 + ty + i) * R + r0 + tx] = __float2half(t[tx][ty + i]);
}

// ============================================================
// prep: wcatT[l][c][d]
// ============================================================
__global__ void prep_wcat_kernel(const float* __restrict__ Woff,
                                 const float* __restrict__ Wattn,
                                 __half* __restrict__ wcatT)
{
    int i = blockIdx.x * 256 + threadIdx.x;
    if (i >= L_ * 128 * D_) return;
    int l = i / (128 * D_);
    int c = (i / D_) % 128;
    int d = i % D_;
    float v = 0.f;
    if (c < 64)      v = Woff[((size_t)l * D_ + d) * 64 + c];
    else if (c < 96) v = Wattn[((size_t)l * D_ + d) * 32 + (c - 64)];
    wcatT[i] = __float2half(v);
}
__global__ void prep_bcat_kernel(const float* __restrict__ boff,
                                 const float* __restrict__ battn,
                                 float* __restrict__ bcat)
{
    int i = threadIdx.x + blockIdx.x * 256;
    if (i >= L_ * 128) return;
    int l = i / 128, c = i % 128;
    float v = 0.f;
    if (c < 64)      v = boff[l * 64 + c];
    else if (c < 96) v = battn[l * 32 + (c - 64)];
    bcat[i] = v;
}

// ============================================================
// q init: broadcast query_embed over batch; fp32 master + fp16 copy
// ============================================================
__global__ void init_q_kernel(const float* __restrict__ qe,
                              float* __restrict__ q, __half* __restrict__ qh)
{
    int i = blockIdx.x * blockDim.x + threadIdx.x;   // over HW_*D_/4
    if (i >= HW_ * D_ / 4) return;
    float4 v = ((const float4*)qe)[i];
    __half2 h0 = __floats2half2_rn(v.x, v.y);
    __half2 h1 = __floats2half2_rn(v.z, v.w);
#pragma unroll
    for (int b = 0; b < B_; b++) {
        ((float4*)q)[(size_t)b * (HW_ * D_ / 4) + i] = v;
        ((__half2*)qh)[((size_t)b * (HW_ * D_ / 4) + i) * 2 + 0] = h0;
        ((__half2*)qh)[((size_t)b * (HW_ * D_ / 4) + i) * 2 + 1] = h1;
    }
}

// ============================================================
// softmax over NP + sample-location compute from GEMM logits
// ============================================================
__global__ void __launch_bounds__(256) postproc_kernel(
    const float* __restrict__ lg, float* __restrict__ loc, float* __restrict__ attw)
{
    int row = blockIdx.x * 8 + (threadIdx.x >> 5);
    int t = threadIdx.x & 31;
    const float* p = lg + (size_t)row * 128;
    int h = t >> 2, pp = t & 3;
    float l0 = p[64 + h * 4 + 0], l1 = p[64 + h * 4 + 1];
    float l2 = p[64 + h * 4 + 2], l3 = p[64 + h * 4 + 3];
    float mx = fmaxf(fmaxf(l0, l1), fmaxf(l2, l3));
    float e0 = expf(l0 - mx), e1 = expf(l1 - mx), e2 = expf(l2 - mx), e3 = expf(l3 - mx);
    float s = e0 + e1 + e2 + e3;
    float my = (pp == 0) ? e0 : (pp == 1) ? e1 : (pp == 2) ? e2 : e3;
    attw[(size_t)row * 32 + t] = my / s;

    float offx = p[(h * 4 + pp) * 2 + 0];
    float offy = p[(h * 4 + pp) * 2 + 1];
    int hw = row & (HW_ - 1);
    float rx = ((hw & (WW_ - 1)) + 0.5f) * (1.f / WW_);
    float ry = ((hw >> 6) + 0.5f) * (1.f / HH_);
    loc[((size_t)row * 32 + t) * 2 + 0] = rx + offx * (1.f / WW_);
    loc[((size_t)row * 32 + t) * 2 + 1] = ry + offy * (1.f / HH_);
}

// ============================================================
// deformable bilinear sampling (fp16 val) + weighted sum -> fp16 samp
// ============================================================
__global__ void __launch_bounds__(256) sample_kernel(
    const __half* __restrict__ val, const float* __restrict__ loc,
    const float* __restrict__ attw, __half* __restrict__ out)
{
    int row = blockIdx.x;
    int b = row >> 12;
    int h = threadIdx.x >> 5;
    int lane = threadIdx.x & 31;

    const float* lp = loc  + ((size_t)row * 32 + h * NP_) * 2;
    const float* wp = attw + (size_t)row * 32 + h * NP_;
    float acc = 0.f;
#pragma unroll
    for (int p = 0; p < NP_; p++) {
        float lx = lp[p * 2 + 0], ly = lp[p * 2 + 1];
        float w = wp[p];
        float gx = lx * WW_ - 0.5f;
        float gy = ly * HH_ - 0.5f;
        float x0f = floorf(gx), y0f = floorf(gy);
        float wx = gx - x0f, wy = gy - y0f;
        int x0 = (int)x0f, y0 = (int)y0f;
        float v = 0.f;
#pragma unroll
        for (int dy = 0; dy < 2; dy++) {
#pragma unroll
            for (int dx = 0; dx < 2; dx++) {
                int xi = x0 + dx, yi = y0 + dy;
                if (xi >= 0 && xi < WW_ && yi >= 0 && yi < HH_) {
                    float cw = (dx ? wx : 1.f - wx) * (dy ? wy : 1.f - wy);
                    v += cw * __half2float(val[((size_t)b * HW_ + yi * WW_ + xi) * D_ + h * 32 + lane]);
                }
            }
        }
        acc += w * v;
    }
    out[(size_t)row * D_ + h * 32 + lane] = __float2half(acc);
}

// ============================================================
// q = LayerNorm(q + delta)*g + b; fp32 master + fp16 copy for GEMMs
// ============================================================
__global__ void __launch_bounds__(256) add_ln_kernel(
    float* __restrict__ q, const float* __restrict__ delta,
    const float* __restrict__ g, const float* __restrict__ b,
    __half* __restrict__ qh)
{
    int row = blockIdx.x;
    int t = threadIdx.x;
    __shared__ float wsum[8];
    __shared__ float s_mean, s_var;
    size_t base = (size_t)row * D_;
    float v = q[base + t] + delta[base + t];

    float r = v;
#pragma unroll
    for (int o = 16; o > 0; o >>= 1) r += __shfl_xor_sync(0xffffffffu, r, o);
    if ((t & 31) == 0) wsum[t >> 5] = r;
    __syncthreads();
    if (t < 8) {
        float x = wsum[t];
#pragma unroll
        for (int o = 4; o > 0; o >>= 1) x += __shfl_xor_sync(0xffu, x, o);
        if (t == 0) s_mean = x * (1.f / D_);
    }
    __syncthreads();
    float d = v - s_mean;
    r = d * d;
#pragma unroll
    for (int o = 16; o > 0; o >>= 1) r += __shfl_xor_sync(0xffffffffu, r, o);
    if ((t & 31) == 0) wsum[t >> 5] = r;
    __syncthreads();
    if (t < 8) {
        float x = wsum[t];
#pragma unroll
        for (int o = 4; o > 0; o >>= 1) x += __shfl_xor_sync(0xffu, x, o);
        if (t == 0) s_var = x * (1.f / D_);
    }
    __syncthreads();
    float o = d * rsqrtf(s_var + EPS_) * g[t] + b[t];
    q[base + t] = o;
    qh[base + t] = __float2half(o);
}

// ============================================================
// host launcher
// ============================================================
extern "C" void kernel_launch(void* const* d_in, const int* in_sizes, int n_in,
                              void* d_out, int out_size)
{
    const float* x      = (const float*)d_in[0];
    const float* W_in   = (const float*)d_in[1];
    const float* bn1_g  = (const float*)d_in[2];
    const float* bn1_b  = (const float*)d_in[3];
    const float* bn1_m  = (const float*)d_in[4];
    const float* bn1_v  = (const float*)d_in[5];
    const float* qembed = (const float*)d_in[6];
    const float* Woff   = (const float*)d_in[7];
    const float* boff   = (const float*)d_in[8];
    const float* Wattn  = (const float*)d_in[9];
    const float* battn  = (const float*)d_in[10];
    const float* Wval   = (const float*)d_in[11];
    const float* bval   = (const float*)d_in[12];
    const float* Wo     = (const float*)d_in[13];
    const float* bo     = (const float*)d_in[14];
    const float* ln1_g  = (const float*)d_in[15];
    const float* ln1_b  = (const float*)d_in[16];
    const float* W1     = (const float*)d_in[17];
    const float* b1     = (const float*)d_in[18];
    const float* W2     = (const float*)d_in[19];
    const float* b2     = (const float*)d_in[20];
    const float* ln2_g  = (const float*)d_in[21];
    const float* ln2_b  = (const float*)d_in[22];
    const float* W_out  = (const float*)d_in[23];
    const float* bn2_g  = (const float*)d_in[24];
    const float* bn2_b  = (const float*)d_in[25];
    const float* bn2_m  = (const float*)d_in[26];
    const float* bn2_v  = (const float*)d_in[27];
    float* out = (float*)d_out;

    float *q, *tmp, *logits, *loc, *attw, *bcat;
    __half *xh, *srch, *qh, *valh, *samph, *ffnh;
    __half *Winh, *Wouth, *WvalT, *WoT, *W1T, *W2T, *wcatT;
    cudaGetSymbolAddress((void**)&q,      g_q);
    cudaGetSymbolAddress((void**)&tmp,    g_tmp);
    cudaGetSymbolAddress((void**)&logits, g_logits);
    cudaGetSymbolAddress((void**)&loc,    g_loc);
    cudaGetSymbolAddress((void**)&attw,   g_attw);
    cudaGetSymbolAddress((void**)&bcat,   g_bcat);
    cudaGetSymbolAddress((void**)&xh,     h_x);
    cudaGetSymbolAddress((void**)&srch,   h_src);
    cudaGetSymbolAddress((void**)&qh,     h_q);
    cudaGetSymbolAddress((void**)&valh,   h_val);
    cudaGetSymbolAddress((void**)&samph,  h_samp);
    cudaGetSymbolAddress((void**)&ffnh,   h_ffn);
    cudaGetSymbolAddress((void**)&Winh,   h_Win);
    cudaGetSymbolAddress((void**)&Wouth,  h_Wout);
    cudaGetSymbolAddress((void**)&WvalT,  h_WvalT);
    cudaGetSymbolAddress((void**)&WoT,    h_WoT);
    cudaGetSymbolAddress((void**)&W1T,    h_W1T);
    cudaGetSymbolAddress((void**)&W2T,    h_W2T);
    cudaGetSymbolAddress((void**)&wcatT,  h_wcatT);

    const int M = B_ * HW_;  // 32768
    dim3 blk(256);
    dim3 tblk(32, 8);
    const int SMEM = 6 * STAGE_H * 2;  // 49152 bytes

    cudaFuncSetAttribute(gemm_h<0,0>, cudaFuncAttributeMaxDynamicSharedMemorySize, SMEM);
    cudaFuncSetAttribute(gemm_h<0,1>, cudaFuncAttributeMaxDynamicSharedMemorySize, SMEM);
    cudaFuncSetAttribute(gemm_h<1,1>, cudaFuncAttributeMaxDynamicSharedMemorySize, SMEM);
    cudaFuncSetAttribute(gemm_h<2,0>, cudaFuncAttributeMaxDynamicSharedMemorySize, SMEM);

    // ---- prep: weight conversion / transposition ----
    cvt_h_kernel<<<(D_*CIN_ + 255)/256, 256>>>(W_in,  Winh,  D_*CIN_);
    cvt_h_kernel<<<(CIN_*D_ + 255)/256, 256>>>(W_out, Wouth, CIN_*D_);
    transpose_h_kernel<<<dim3(D_/32, D_/32, L_), tblk>>>(Wval, WvalT, D_, D_, (size_t)D_*D_, (size_t)D_*D_);
    transpose_h_kernel<<<dim3(DFF_/32, D_/32, L_), tblk>>>(W1, W1T, D_, DFF_, (size_t)D_*DFF_, (size_t)D_*DFF_);
    transpose_h_kernel<<<dim3(D_/32, DFF_/32, L_), tblk>>>(W2, W2T, DFF_, D_, (size_t)DFF_*D_, (size_t)DFF_*D_);
    transpose_h_kernel<<<dim3(D_/32, D_/32, L_), tblk>>>(Wo, WoT, D_, D_, (size_t)D_*D_, (size_t)D_*D_);
    transpose_h_kernel<<<dim3(HW_/32, CIN_/32, B_), tblk>>>(x, xh, CIN_, HW_, (size_t)CIN_*HW_, (size_t)CIN_*HW_);
    prep_wcat_kernel<<<(L_*128*D_ + 255)/256, 256>>>(Woff, Wattn, wcatT);
    prep_bcat_kernel<<<1, 256>>>(boff, battn, bcat);

    // proj_in: A = xh[b] (HW x CIN), B = Winh (D x CIN), BN per-n + relu -> src fp16
    gemm_h<1, 1><<<dim3(HW_/BM, D_/BN, B_), blk, SMEM>>>(
        xh, CIN_, (size_t)HW_*CIN_,
        Winh, CIN_, 0,
        srch, D_, (size_t)HW_*D_,
        bn1_g, bn1_b, bn1_m, bn1_v, CIN_, 0);

    init_q_kernel<<<(HW_*D_/4 + 255)/256, 256>>>(qembed, q, qh);

    for (int l = 0; l < L_; l++) {
        gemm_h<0, 1><<<dim3(M/BM, D_/BN, 1), blk, SMEM>>>(
            srch, D_, 0, WvalT + (size_t)l*D_*D_, D_, 0,
            valh, D_, 0, bval + l*D_, nullptr, nullptr, nullptr, D_, 0);

        gemm_h<0, 0><<<dim3(M/BM, 1, 1), blk, SMEM>>>(
            qh, D_, 0, wcatT + (size_t)l*128*D_, D_, 0,
            logits, 128, 0, bcat + l*128, nullptr, nullptr, nullptr, D_, 0);

        postproc_kernel<<<M/8, 256>>>(logits, loc, attw);

        sample_kernel<<<M, 256>>>(valh, loc, attw, samph);

        gemm_h<0, 0><<<dim3(M/BM, D_/BN, 1), blk, SMEM>>>(
            samph, D_, 0, WoT + (size_t)l*D_*D_, D_, 0,
            tmp, D_, 0, bo + l*D_, nullptr, nullptr, nullptr, D_, 0);

        add_ln_kernel<<<M, D_>>>(q, tmp, ln1_g + l*D_, ln1_b + l*D_, qh);

        gemm_h<0, 1><<<dim3(M/BM, DFF_/BN, 1), blk, SMEM>>>(
            qh, D_, 0, W1T + (size_t)l*DFF_*D_, D_, 0,
            ffnh, DFF_, 0, b1 + l*DFF_, nullptr, nullptr, nullptr, D_, 1);

        gemm_h<0, 0><<<dim3(M/BM, D_/BN, 1), blk, SMEM>>>(
            ffnh, DFF_, 0, W2T + (size_t)l*D_*DFF_, DFF_, 0,
            tmp, D_, 0, b2 + l*D_, nullptr, nullptr, nullptr, DFF_, 0);

        add_ln_kernel<<<M, D_>>>(q, tmp, ln2_g + l*D_, ln2_b + l*D_, qh);
    }

    // proj_out: A = Wouth (CIN x D), B = qh[b] (HW x D), BN per-m + relu -> out fp32
    gemm_h<2, 0><<<dim3(CIN_/BM, HW_/BN, B_), blk, SMEM>>>(
        Wouth, D_, 0,
        qh, D_, (size_t)HW_*D_,
        out, HW_, (size_t)CIN_*HW_,
        bn2_g, bn2_b, bn2_m, bn2_v, D_, 0);
}

// round 17
// speedup vs baseline: 1.3750x; 1.3750x over previous
#include <cuda_runtime.h>
#include <cuda_fp16.h>
#include <math.h>
#include <stdint.h>

// ---------------- problem constants ----------------
#define L_    2
#define D_    256
#define DFF_  1024
#define NH_   8
#define NP_   4
#define CIN_  512
#define B_    8
#define HH_   64
#define WW_   64
#define HW_   4096
#define EPS_  1e-5f

// ---------------- GEMM tiling ----------------
#define BM 128
#define BN 128
#define BK 32
#define ASTR 40              // halfs per smem row (32 data + 8 pad)
#define STAGE_H (BM * ASTR)  // 5120 halfs = 10KB per stage

// ---------------- scratch (device globals; allocation-free) ----------------
__device__ __align__(128) float  g_q     [B_*HW_*D_];
__device__ __align__(128) float  g_loc   [B_*HW_*NH_*NP_*2];
__device__ __align__(128) float  g_attw  [B_*HW_*NH_*NP_];
__device__ __align__(128) float  g_bcat  [L_*128];

__device__ __align__(128) __half h_x    [B_*HW_*CIN_];
__device__ __align__(128) __half h_src  [B_*HW_*D_];
__device__ __align__(128) __half h_q    [B_*HW_*D_];
__device__ __align__(128) __half h_val  [B_*HW_*D_];
__device__ __align__(128) __half h_samp [B_*HW_*D_];
__device__ __align__(128) __half h_ffn  [B_*HW_*DFF_];

__device__ __align__(128) __half h_Win  [D_*CIN_];
__device__ __align__(128) __half h_Wout [CIN_*D_];
__device__ __align__(128) __half h_WvalT[L_*D_*D_];
__device__ __align__(128) __half h_WoT  [L_*D_*D_];
__device__ __align__(128) __half h_W1T  [L_*DFF_*D_];
__device__ __align__(128) __half h_W2T  [L_*D_*DFF_];
__device__ __align__(128) __half h_wcatT[L_*128*D_];

// ---------------- helpers ----------------
__device__ __forceinline__ void cp16(void* dst, const void* src) {
    uint32_t d = (uint32_t)__cvta_generic_to_shared(dst);
    asm volatile("cp.async.cg.shared.global [%0], [%1], 16;\n" :: "r"(d), "l"(src));
}
__device__ __forceinline__ void mma16(float* c, const uint32_t* a, const uint32_t* b) {
    asm volatile(
        "mma.sync.aligned.m16n8k16.row.col.f32.f16.f16.f32 "
        "{%0,%1,%2,%3},{%4,%5,%6,%7},{%8,%9},{%0,%1,%2,%3};"
        : "+f"(c[0]), "+f"(c[1]), "+f"(c[2]), "+f"(c[3])
        : "r"(a[0]), "r"(a[1]), "r"(a[2]), "r"(a[3]), "r"(b[0]), "r"(b[1]));
}

// ============================================================
// fp16 tensor-core GEMM (R11 mainloop). C[M,N] = A[M,K] @ B^T + epilogue
//  A: fp16 row-major [M][K] (lda); B: fp16 [N][K] (ldb) -> .col operand
//  EPI 0: +bias(opt relu); 1: BN per-n + relu; 2: BN per-m + relu;
//  EPI 3: logits -> fused softmax/loc/attw (p0=bias, p1=loc, p2=attw; no C store)
//  OUTH 1: store fp16; 0: store fp32
// 3-stage cp.async, tile 128x128x32, 8 warps (2x4), warp tile 64x32.
// ============================================================
template<int EPI, int OUTH>
__global__ void __launch_bounds__(256) gemm_h(
    const __half* __restrict__ A, int lda, size_t sA,
    const __half* __restrict__ Bh, int ldb, size_t sB,
    void* __restrict__ C, int ldc, size_t sC,
    const float* __restrict__ p0, const float* __restrict__ p1,
    const float* __restrict__ p2, const float* __restrict__ p3,
    int K, int relu)
{
    extern __shared__ __half smem[];
    __half* As = smem;                       // 3 stages of STAGE_H
    __half* Bs = smem + 3 * STAGE_H;

    int tid = threadIdx.x;
    int bm = blockIdx.x * BM, bn = blockIdx.y * BN;
    const __half* Ab = A  + (size_t)blockIdx.z * sA;
    const __half* Bb = Bh + (size_t)blockIdx.z * sB;

    float acc[4][4][4];
#pragma unroll
    for (int i = 0; i < 4; i++)
#pragma unroll
        for (int j = 0; j < 4; j++)
#pragma unroll
            for (int r = 0; r < 4; r++) acc[i][j][r] = 0.f;

    int lane = tid & 31, wid = tid >> 5;
    int wm = (wid >> 2) * 64, wn = (wid & 3) * 32;
    int grp = lane >> 2, tig = lane & 3;

    auto stage = [&](int s, int k0) {
        __half* Asl = As + s * STAGE_H;
        __half* Bsl = Bs + s * STAGE_H;
#pragma unroll
        for (int id = tid; id < 512; id += 256) {
            int r = id >> 2, kc = (id & 3) << 3;
            cp16(&Asl[r * ASTR + kc], Ab + (size_t)(bm + r) * lda + k0 + kc);
        }
#pragma unroll
        for (int id = tid; id < 512; id += 256) {
            int r = id >> 2, kc = (id & 3) << 3;
            cp16(&Bsl[r * ASTR + kc], Bb + (size_t)(bn + r) * ldb + k0 + kc);
        }
        asm volatile("cp.async.commit_group;\n");
    };

    stage(0, 0);
    stage(1, BK);

    int slot = 0;
    for (int k0 = 0; k0 < K; k0 += BK) {
        if (k0 + BK < K) asm volatile("cp.async.wait_group 1;\n");
        else             asm volatile("cp.async.wait_group 0;\n");
        __syncthreads();
        if (k0 + 2 * BK < K) {
            int ns = slot + 2; if (ns >= 3) ns -= 3;
            stage(ns, k0 + 2 * BK);
        }

        const uint32_t* Aw = (const uint32_t*)(As + slot * STAGE_H);
        const uint32_t* Bw = (const uint32_t*)(Bs + slot * STAGE_H);
#pragma unroll
        for (int ks = 0; ks < 2; ks++) {
            uint32_t af[4][4], bf[4][2];
            int kb = ks * 8 + tig;
#pragma unroll
            for (int mt = 0; mt < 4; mt++) {
                int r0 = wm + mt * 16 + grp;
                int base = r0 * (ASTR / 2) + kb;
                af[mt][0] = Aw[base];
                af[mt][1] = Aw[base + 8 * (ASTR / 2)];
                af[mt][2] = Aw[base + 4];
                af[mt][3] = Aw[base + 8 * (ASTR / 2) + 4];
            }
#pragma unroll
            for (int nt = 0; nt < 4; nt++) {
                int n0 = wn + nt * 8 + grp;
                int base = n0 * (ASTR / 2) + kb;
                bf[nt][0] = Bw[base];
                bf[nt][1] = Bw[base + 4];
            }
#pragma unroll
            for (int mt = 0; mt < 4; mt++)
#pragma unroll
                for (int nt = 0; nt < 4; nt++)
                    mma16(acc[mt][nt], af[mt], bf[nt]);
        }
        slot++; if (slot >= 3) slot -= 3;
    }

    // ---------------- epilogue ----------------
    float* ls = (float*)smem;   // EPI3: 128 rows x 96 cols (stride 100)
    if (EPI == 3) __syncthreads();   // stage smem dead -> reuse

#pragma unroll
    for (int mt = 0; mt < 4; mt++) {
#pragma unroll
        for (int nt = 0; nt < 4; nt++) {
            int gm = bm + wm + mt * 16 + grp;
            int gn = bn + wn + nt * 8 + tig * 2;
            float* c = acc[mt][nt];
#pragma unroll
            for (int half = 0; half < 2; half++) {
                int row = gm + half * 8;
                float v0 = c[half * 2 + 0], v1 = c[half * 2 + 1];
                if (EPI == 0 || EPI == 3) {
                    v0 += p0[gn]; v1 += p0[gn + 1];
                    if (EPI == 0 && relu) { v0 = fmaxf(v0, 0.f); v1 = fmaxf(v1, 0.f); }
                } else if (EPI == 1) {
                    float s0 = rsqrtf(p3[gn] + EPS_) * p0[gn];
                    float s1 = rsqrtf(p3[gn + 1] + EPS_) * p0[gn + 1];
                    v0 = fmaxf((v0 - p2[gn]) * s0 + p1[gn], 0.f);
                    v1 = fmaxf((v1 - p2[gn + 1]) * s1 + p1[gn + 1], 0.f);
                } else if (EPI == 2) {
                    float s = rsqrtf(p3[row] + EPS_) * p0[row];
                    float h = p1[row] - p2[row] * s;
                    v0 = fmaxf(v0 * s + h, 0.f);
                    v1 = fmaxf(v1 * s + h, 0.f);
                }
                if (EPI == 3) {
                    int lrow = wm + mt * 16 + grp + half * 8;
                    if (gn < 96) {
                        ls[lrow * 100 + gn] = v0;
                        ls[lrow * 100 + gn + 1] = v1;
                    }
                } else {
                    size_t off = (size_t)blockIdx.z * sC + (size_t)row * ldc + gn;
                    if (OUTH) {
                        __half2 hv = __floats2half2_rn(v0, v1);
                        *(__half2*)((__half*)C + off) = hv;
                    } else {
                        float2 o; o.x = v0; o.y = v1;
                        *(float2*)((float*)C + off) = o;
                    }
                }
            }
        }
    }

    if (EPI == 3) {
        __syncthreads();
        float* locp  = (float*)p1;
        float* attp  = (float*)p2;
        int h = lane >> 2, pp = lane & 3;
#pragma unroll
        for (int rr = 0; rr < 16; rr++) {
            int lrow = wid * 16 + rr;
            int grow = bm + lrow;
            const float* pl = ls + lrow * 100;
            float l0 = pl[64 + h * 4 + 0], l1 = pl[64 + h * 4 + 1];
            float l2 = pl[64 + h * 4 + 2], l3 = pl[64 + h * 4 + 3];
            float mx = fmaxf(fmaxf(l0, l1), fmaxf(l2, l3));
            float e0 = expf(l0 - mx), e1 = expf(l1 - mx);
            float e2 = expf(l2 - mx), e3 = expf(l3 - mx);
            float s = e0 + e1 + e2 + e3;
            float my = (pp == 0) ? e0 : (pp == 1) ? e1 : (pp == 2) ? e2 : e3;
            attp[(size_t)grow * 32 + lane] = my / s;

            float offx = pl[(h * 4 + pp) * 2 + 0];
            float offy = pl[(h * 4 + pp) * 2 + 1];
            int hw = grow & (HW_ - 1);
            float rx = ((hw & (WW_ - 1)) + 0.5f) * (1.f / WW_);
            float ry = ((hw >> 6) + 0.5f) * (1.f / HH_);
            float2 lv;
            lv.x = rx + offx * (1.f / WW_);
            lv.y = ry + offy * (1.f / HH_);
            *(float2*)&locp[((size_t)grow * 32 + lane) * 2] = lv;
        }
    }
}

// ============================================================
// fused GEMM + residual + LayerNorm (Wo and W2 paths).
// C'[M,256] = A[M,K] @ B^T + bias;  q = LN(q + C')*g + b; qh = fp16(q)
// BM=128, BN=256 (full row), BK=32, 512 thr (16 warps 2x8), warp 64x32.
// 3-stage cp.async.
// ============================================================
__global__ void __launch_bounds__(512) gemm_ln(
    const __half* __restrict__ A, int lda,
    const __half* __restrict__ Bh, int ldb,
    const float* __restrict__ bias,
    const float* __restrict__ g, const float* __restrict__ b,
    float* __restrict__ q, __half* __restrict__ qh, int K)
{
    // A stage: 128x40 halfs (5120); B stage: 256x40 halfs (10240); 3 stages each
    extern __shared__ __half smem[];
    __half* As = smem;                 // 3 x 5120
    __half* Bs = smem + 3 * 5120;      // 3 x 10240

    int tid = threadIdx.x;
    int lane = tid & 31, wid = tid >> 5;
    int bm = blockIdx.x * BM;
    int wm = (wid >> 3) * 64, wn = (wid & 7) * 32;
    int grp = lane >> 2, tig = lane & 3;

    float acc[4][4][4];
#pragma unroll
    for (int i = 0; i < 4; i++)
#pragma unroll
        for (int j = 0; j < 4; j++)
#pragma unroll
            for (int r = 0; r < 4; r++) acc[i][j][r] = 0.f;

    auto stage = [&](int s, int k0) {
        __half* Asl = As + s * 5120;
        __half* Bsl = Bs + s * 10240;
        {
            int r = tid >> 2, kc = (tid & 3) << 3;
            cp16(&Asl[r * ASTR + kc], A + (size_t)(bm + r) * lda + k0 + kc);
        }
#pragma unroll
        for (int id = tid; id < 1024; id += 512) {
            int r = id >> 2, kc = (id & 3) << 3;
            cp16(&Bsl[r * ASTR + kc], Bh + (size_t)r * ldb + k0 + kc);
        }
        asm volatile("cp.async.commit_group;\n");
    };

    stage(0, 0);
    stage(1, BK);

    int slot = 0;
    for (int k0 = 0; k0 < K; k0 += BK) {
        if (k0 + BK < K) asm volatile("cp.async.wait_group 1;\n");
        else             asm volatile("cp.async.wait_group 0;\n");
        __syncthreads();
        if (k0 + 2 * BK < K) {
            int ns = slot + 2; if (ns >= 3) ns -= 3;
            stage(ns, k0 + 2 * BK);
        }

        const uint32_t* Aw = (const uint32_t*)(As + slot * 5120);
        const uint32_t* Bw = (const uint32_t*)(Bs + slot * 10240);
#pragma unroll
        for (int ks = 0; ks < 2; ks++) {
            uint32_t af[4][4], bf[4][2];
            int kb = ks * 8 + tig;
#pragma unroll
            for (int mt = 0; mt < 4; mt++) {
                int r0 = wm + mt * 16 + grp;
                int base = r0 * (ASTR / 2) + kb;
                af[mt][0] = Aw[base];
                af[mt][1] = Aw[base + 8 * (ASTR / 2)];
                af[mt][2] = Aw[base + 4];
                af[mt][3] = Aw[base + 8 * (ASTR / 2) + 4];
            }
#pragma unroll
            for (int nt = 0; nt < 4; nt++) {
                int n0 = wn + nt * 8 + grp;
                int base = n0 * (ASTR / 2) + kb;
                bf[nt][0] = Bw[base];
                bf[nt][1] = Bw[base + 4];
            }
#pragma unroll
            for (int mt = 0; mt < 4; mt++)
#pragma unroll
                for (int nt = 0; nt < 4; nt++)
                    mma16(acc[mt][nt], af[mt], bf[nt]);
        }
        slot++; if (slot >= 3) slot -= 3;
    }

    __syncthreads();               // stage smem dead -> reuse for reductions
    float* red = (float*)smem;     // [128][8]

    // pass 1: v = q + acc + bias; row partial sums
    float mean[4][2];
#pragma unroll
    for (int mt = 0; mt < 4; mt++) {
#pragma unroll
        for (int half = 0; half < 2; half++) {
            int row = wm + mt * 16 + half * 8 + grp;
            size_t grow = (size_t)(bm + row);
            float ps = 0.f;
#pragma unroll
            for (int nt = 0; nt < 4; nt++) {
                int gn = wn + nt * 8 + tig * 2;
                float v0 = acc[mt][nt][half * 2 + 0] + bias[gn]     + q[grow * D_ + gn];
                float v1 = acc[mt][nt][half * 2 + 1] + bias[gn + 1] + q[grow * D_ + gn + 1];
                acc[mt][nt][half * 2 + 0] = v0;
                acc[mt][nt][half * 2 + 1] = v1;
                ps += v0 + v1;
            }
            ps += __shfl_xor_sync(0xffffffffu, ps, 1);
            ps += __shfl_xor_sync(0xffffffffu, ps, 2);
            if (tig == 0) red[row * 8 + (wid & 7)] = ps;
        }
    }
    __syncthreads();
#pragma unroll
    for (int mt = 0; mt < 4; mt++)
#pragma unroll
        for (int half = 0; half < 2; half++) {
            int row = wm + mt * 16 + half * 8 + grp;
            float s = 0.f;
#pragma unroll
            for (int j = 0; j < 8; j++) s += red[row * 8 + j];
            mean[mt][half] = s * (1.f / D_);
        }
    __syncthreads();

    // pass 2: variance
    float rstd[4][2];
#pragma unroll
    for (int mt = 0; mt < 4; mt++) {
#pragma unroll
        for (int half = 0; half < 2; half++) {
            int row = wm + mt * 16 + half * 8 + grp;
            float m = mean[mt][half];
            float vs = 0.f;
#pragma unroll
            for (int nt = 0; nt < 4; nt++) {
                float d0 = acc[mt][nt][half * 2 + 0] - m;
                float d1 = acc[mt][nt][half * 2 + 1] - m;
                vs += d0 * d0 + d1 * d1;
            }
            vs += __shfl_xor_sync(0xffffffffu, vs, 1);
            vs += __shfl_xor_sync(0xffffffffu, vs, 2);
            if (tig == 0) red[row * 8 + (wid & 7)] = vs;
        }
    }
    __syncthreads();
#pragma unroll
    for (int mt = 0; mt < 4; mt++)
#pragma unroll
        for (int half = 0; half < 2; half++) {
            int row = wm + mt * 16 + half * 8 + grp;
            float s = 0.f;
#pragma unroll
            for (int j = 0; j < 8; j++) s += red[row * 8 + j];
            rstd[mt][half] = rsqrtf(s * (1.f / D_) + EPS_);
        }

    // final: normalize + affine; write q fp32 + qh fp16
#pragma unroll
    for (int mt = 0; mt < 4; mt++) {
#pragma unroll
        for (int half = 0; half < 2; half++) {
            int row = wm + mt * 16 + half * 8 + grp;
            size_t grow = (size_t)(bm + row);
            float m = mean[mt][half], r = rstd[mt][half];
#pragma unroll
            for (int nt = 0; nt < 4; nt++) {
                int gn = wn + nt * 8 + tig * 2;
                float o0 = (acc[mt][nt][half * 2 + 0] - m) * r * g[gn]     + b[gn];
                float o1 = (acc[mt][nt][half * 2 + 1] - m) * r * g[gn + 1] + b[gn + 1];
                float2 of; of.x = o0; of.y = o1;
                *(float2*)&q[grow * D_ + gn] = of;
                __half2 hv = __floats2half2_rn(o0, o1);
                *(__half2*)&qh[grow * D_ + gn] = hv;
            }
        }
    }
}

// ============================================================
// prep kernels
// ============================================================
__global__ void cvt_h_kernel(const float* __restrict__ src, __half* __restrict__ dst, int n)
{
    int i = blockIdx.x * blockDim.x + threadIdx.x;
    if (i < n) dst[i] = __float2half(src[i]);
}

__global__ void transpose_h_kernel(const float* __restrict__ src, __half* __restrict__ dst,
                                   int R, int C, size_t ssrc, size_t sdst)
{
    __shared__ float t[32][33];
    const float* s = src + (size_t)blockIdx.z * ssrc;
    __half* d = dst + (size_t)blockIdx.z * sdst;
    int r0 = blockIdx.y * 32, c0 = blockIdx.x * 32;
    int tx = threadIdx.x, ty = threadIdx.y;
#pragma unroll
    for (int i = 0; i < 32; i += 8)
        t[ty + i][tx] = s[(size_t)(r0 + ty + i) * C + c0 + tx];
    __syncthreads();
#pragma unroll
    for (int i = 0; i < 32; i += 8)
        d[(size_t)(c0 + ty + i) * R + r0 + tx] = __float2half(t[tx][ty + i]);
}

__global__ void prep_wcat_kernel(const float* __restrict__ Woff,
                                 const float* __restrict__ Wattn,
                                 __half* __restrict__ wcatT)
{
    int i = blockIdx.x * 256 + threadIdx.x;
    if (i >= L_ * 128 * D_) return;
    int l = i / (128 * D_);
    int c = (i / D_) % 128;
    int d = i % D_;
    float v = 0.f;
    if (c < 64)      v = Woff[((size_t)l * D_ + d) * 64 + c];
    else if (c < 96) v = Wattn[((size_t)l * D_ + d) * 32 + (c - 64)];
    wcatT[i] = __float2half(v);
}
__global__ void prep_bcat_kernel(const float* __restrict__ boff,
                                 const float* __restrict__ battn,
                                 float* __restrict__ bcat)
{
    int i = threadIdx.x + blockIdx.x * 256;
    if (i >= L_ * 128) return;
    int l = i / 128, c = i % 128;
    float v = 0.f;
    if (c < 64)      v = boff[l * 64 + c];
    else if (c < 96) v = battn[l * 32 + (c - 64)];
    bcat[i] = v;
}

__global__ void init_q_kernel(const float* __restrict__ qe,
                              float* __restrict__ q, __half* __restrict__ qh)
{
    int i = blockIdx.x * blockDim.x + threadIdx.x;
    if (i >= HW_ * D_ / 4) return;
    float4 v = ((const float4*)qe)[i];
    __half2 h0 = __floats2half2_rn(v.x, v.y);
    __half2 h1 = __floats2half2_rn(v.z, v.w);
#pragma unroll
    for (int b = 0; b < B_; b++) {
        ((float4*)q)[(size_t)b * (HW_ * D_ / 4) + i] = v;
        ((__half2*)qh)[((size_t)b * (HW_ * D_ / 4) + i) * 2 + 0] = h0;
        ((__half2*)qh)[((size_t)b * (HW_ * D_ / 4) + i) * 2 + 1] = h1;
    }
}

// ============================================================
// deformable bilinear sampling (fp16 val) + weighted sum -> fp16 samp
// ============================================================
__global__ void __launch_bounds__(256) sample_kernel(
    const __half* __restrict__ val, const float* __restrict__ loc,
    const float* __restrict__ attw, __half* __restrict__ out)
{
    int row = blockIdx.x;
    int b = row >> 12;
    int h = threadIdx.x >> 5;
    int lane = threadIdx.x & 31;

    const float* lp = loc  + ((size_t)row * 32 + h * NP_) * 2;
    const float* wp = attw + (size_t)row * 32 + h * NP_;
    float acc = 0.f;
#pragma unroll
    for (int p = 0; p < NP_; p++) {
        float lx = lp[p * 2 + 0], ly = lp[p * 2 + 1];
        float w = wp[p];
        float gx = lx * WW_ - 0.5f;
        float gy = ly * HH_ - 0.5f;
        float x0f = floorf(gx), y0f = floorf(gy);
        float wx = gx - x0f, wy = gy - y0f;
        int x0 = (int)x0f, y0 = (int)y0f;
        float v = 0.f;
#pragma unroll
        for (int dy = 0; dy < 2; dy++) {
#pragma unroll
            for (int dx = 0; dx < 2; dx++) {
                int xi = x0 + dx, yi = y0 + dy;
                if (xi >= 0 && xi < WW_ && yi >= 0 && yi < HH_) {
                    float cw = (dx ? wx : 1.f - wx) * (dy ? wy : 1.f - wy);
                    v += cw * __half2float(val[((size_t)b * HW_ + yi * WW_ + xi) * D_ + h * 32 + lane]);
                }
            }
        }
        acc += w * v;
    }
    out[(size_t)row * D_ + h * 32 + lane] = __float2half(acc);
}

// ============================================================
// host launcher
// ============================================================
extern "C" void kernel_launch(void* const* d_in, const int* in_sizes, int n_in,
                              void* d_out, int out_size)
{
    const float* x      = (const float*)d_in[0];
    const float* W_in   = (const float*)d_in[1];
    const float* bn1_g  = (const float*)d_in[2];
    const float* bn1_b  = (const float*)d_in[3];
    const float* bn1_m  = (const float*)d_in[4];
    const float* bn1_v  = (const float*)d_in[5];
    const float* qembed = (const float*)d_in[6];
    const float* Woff   = (const float*)d_in[7];
    const float* boff   = (const float*)d_in[8];
    const float* Wattn  = (const float*)d_in[9];
    const float* battn  = (const float*)d_in[10];
    const float* Wval   = (const float*)d_in[11];
    const float* bval   = (const float*)d_in[12];
    const float* Wo     = (const float*)d_in[13];
    const float* bo     = (const float*)d_in[14];
    const float* ln1_g  = (const float*)d_in[15];
    const float* ln1_b  = (const float*)d_in[16];
    const float* W1     = (const float*)d_in[17];
    const float* b1     = (const float*)d_in[18];
    const float* W2     = (const float*)d_in[19];
    const float* b2     = (const float*)d_in[20];
    const float* ln2_g  = (const float*)d_in[21];
    const float* ln2_b  = (const float*)d_in[22];
    const float* W_out  = (const float*)d_in[23];
    const float* bn2_g  = (const float*)d_in[24];
    const float* bn2_b  = (const float*)d_in[25];
    const float* bn2_m  = (const float*)d_in[26];
    const float* bn2_v  = (const float*)d_in[27];
    float* out = (float*)d_out;

    float *q, *loc, *attw, *bcat;
    __half *xh, *srch, *qh, *valh, *samph, *ffnh;
    __half *Winh, *Wouth, *WvalT, *WoT, *W1T, *W2T, *wcatT;
    cudaGetSymbolAddress((void**)&q,      g_q);
    cudaGetSymbolAddress((void**)&loc,    g_loc);
    cudaGetSymbolAddress((void**)&attw,   g_attw);
    cudaGetSymbolAddress((void**)&bcat,   g_bcat);
    cudaGetSymbolAddress((void**)&xh,     h_x);
    cudaGetSymbolAddress((void**)&srch,   h_src);
    cudaGetSymbolAddress((void**)&qh,     h_q);
    cudaGetSymbolAddress((void**)&valh,   h_val);
    cudaGetSymbolAddress((void**)&samph,  h_samp);
    cudaGetSymbolAddress((void**)&ffnh,   h_ffn);
    cudaGetSymbolAddress((void**)&Winh,   h_Win);
    cudaGetSymbolAddress((void**)&Wouth,  h_Wout);
    cudaGetSymbolAddress((void**)&WvalT,  h_WvalT);
    cudaGetSymbolAddress((void**)&WoT,    h_WoT);
    cudaGetSymbolAddress((void**)&W1T,    h_W1T);
    cudaGetSymbolAddress((void**)&W2T,    h_W2T);
    cudaGetSymbolAddress((void**)&wcatT,  h_wcatT);

    const int M = B_ * HW_;  // 32768
    dim3 blk(256);
    dim3 tblk(32, 8);
    const int SMEM    = 6 * STAGE_H * 2;              // 61440 bytes
    const int SMEM_LN = 3 * (5120 + 10240) * 2;       // 92160 bytes

    cudaFuncSetAttribute(gemm_h<0,0>, cudaFuncAttributeMaxDynamicSharedMemorySize, SMEM);
    cudaFuncSetAttribute(gemm_h<0,1>, cudaFuncAttributeMaxDynamicSharedMemorySize, SMEM);
    cudaFuncSetAttribute(gemm_h<1,1>, cudaFuncAttributeMaxDynamicSharedMemorySize, SMEM);
    cudaFuncSetAttribute(gemm_h<2,0>, cudaFuncAttributeMaxDynamicSharedMemorySize, SMEM);
    cudaFuncSetAttribute(gemm_h<3,0>, cudaFuncAttributeMaxDynamicSharedMemorySize, SMEM);
    cudaFuncSetAttribute(gemm_ln,     cudaFuncAttributeMaxDynamicSharedMemorySize, SMEM_LN);

    // ---- prep: weight conversion / transposition ----
    cvt_h_kernel<<<(D_*CIN_ + 255)/256, 256>>>(W_in,  Winh,  D_*CIN_);
    cvt_h_kernel<<<(CIN_*D_ + 255)/256, 256>>>(W_out, Wouth, CIN_*D_);
    transpose_h_kernel<<<dim3(D_/32, D_/32, L_), tblk>>>(Wval, WvalT, D_, D_, (size_t)D_*D_, (size_t)D_*D_);
    transpose_h_kernel<<<dim3(DFF_/32, D_/32, L_), tblk>>>(W1, W1T, D_, DFF_, (size_t)D_*DFF_, (size_t)D_*DFF_);
    transpose_h_kernel<<<dim3(D_/32, DFF_/32, L_), tblk>>>(W2, W2T, DFF_, D_, (size_t)DFF_*D_, (size_t)DFF_*D_);
    transpose_h_kernel<<<dim3(D_/32, D_/32, L_), tblk>>>(Wo, WoT, D_, D_, (size_t)D_*D_, (size_t)D_*D_);
    transpose_h_kernel<<<dim3(HW_/32, CIN_/32, B_), tblk>>>(x, xh, CIN_, HW_, (size_t)CIN_*HW_, (size_t)CIN_*HW_);
    prep_wcat_kernel<<<(L_*128*D_ + 255)/256, 256>>>(Woff, Wattn, wcatT);
    prep_bcat_kernel<<<1, 256>>>(boff, battn, bcat);

    // proj_in: A = xh[b] (HW x CIN), B = Winh (D x CIN), BN per-n + relu -> src fp16
    gemm_h<1, 1><<<dim3(HW_/BM, D_/BN, B_), blk, SMEM>>>(
        xh, CIN_, (size_t)HW_*CIN_,
        Winh, CIN_, 0,
        srch, D_, (size_t)HW_*D_,
        bn1_g, bn1_b, bn1_m, bn1_v, CIN_, 0);

    init_q_kernel<<<(HW_*D_/4 + 255)/256, 256>>>(qembed, q, qh);

    for (int l = 0; l < L_; l++) {
        gemm_h<0, 1><<<dim3(M/BM, D_/BN, 1), blk, SMEM>>>(
            srch, D_, 0, WvalT + (size_t)l*D_*D_, D_, 0,
            valh, D_, 0, bval + l*D_, nullptr, nullptr, nullptr, D_, 0);

        // fused offsets/attn logits + softmax + loc (EPI=3)
        gemm_h<3, 0><<<dim3(M/BM, 1, 1), blk, SMEM>>>(
            qh, D_, 0, wcatT + (size_t)l*128*D_, D_, 0,
            nullptr, 128, 0, bcat + l*128, loc, attw, nullptr, D_, 0);

        sample_kernel<<<M, 256>>>(valh, loc, attw, samph);

        // Wo GEMM + residual + LN1 (fused)
        gemm_ln<<<M/BM, 512, SMEM_LN>>>(
            samph, D_, WoT + (size_t)l*D_*D_, D_,
            bo + l*D_, ln1_g + l*D_, ln1_b + l*D_, q, qh, D_);

        gemm_h<0, 1><<<dim3(M/BM, DFF_/BN, 1), blk, SMEM>>>(
            qh, D_, 0, W1T + (size_t)l*DFF_*D_, D_, 0,
            ffnh, DFF_, 0, b1 + l*DFF_, nullptr, nullptr, nullptr, D_, 1);

        // W2 GEMM + residual + LN2 (fused)
        gemm_ln<<<M/BM, 512, SMEM_LN>>>(
            ffnh, DFF_, W2T + (size_t)l*D_*DFF_, DFF_,
            b2 + l*D_, ln2_g + l*D_, ln2_b + l*D_, q, qh, DFF_);
    }

    // proj_out: A = Wouth (CIN x D), B = qh[b] (HW x D), BN per-m + relu -> out fp32
    gemm_h<2, 0><<<dim3(CIN_/BM, HW_/BN, B_), blk, SMEM>>>(
        Wouth, D_, 0,
        qh, D_, (size_t)HW_*D_,
        out, HW_, (size_t)CIN_*HW_,
        bn2_g, bn2_b, bn2_m, bn2_v, D_, 0);
}